// round 1
// baseline (speedup 1.0000x reference)
#include <cuda_runtime.h>

// DotAttention: rnn_out [S,B,H] f32, state [2,2,B,H/2] f32 -> out [B,H,1] f32
// S=2048, B=32, H=1024.
// merged[b, d*512+hh] = state[1, d, b, hh]
// scores[b,s] = sum_h rnn_out[s,b,h]*merged[b,h]; w = softmax_s(scores)
// out[b,h]    = sum_s rnn_out[s,b,h]*w[b,s]
//
// Single-pass online softmax (flash style), split over S. One warp handles one
// (b, s-chunk) pair with register-resident acc[1024] (8 x float4 per lane).

#define S_LEN 2048
#define B_DIM 32
#define H_DIM 1024
#define SPLIT 128
#define CHUNK (S_LEN / SPLIT)          // 16 rows per warp
#define WARPS_PER_CTA 8
#define NPART (B_DIM * SPLIT)          // 4096 partials

__device__ float g_m[NPART];
__device__ float g_l[NPART];
__device__ float g_acc[(size_t)NPART * H_DIM];   // ~16.8 MB scratch

__global__ __launch_bounds__(256) void pass1(const float* __restrict__ rnn,
                                             const float* __restrict__ state) {
    const int warp = blockIdx.x * WARPS_PER_CTA + (threadIdx.x >> 5);
    const int lane = threadIdx.x & 31;
    const int b = warp / SPLIT;
    const int chunk = warp % SPLIT;

    // Load merged[b, :] : lane owns h = j*128 + lane*4 .. +3
    float4 mrg[8];
#pragma unroll
    for (int j = 0; j < 8; j++) {
        int h = j * 128 + lane * 4;
        int d = h >> 9;          // direction: 0 for h<512, 1 otherwise
        int hh = h & 511;
        mrg[j] = *reinterpret_cast<const float4*>(
            state + (size_t)(2 + d) * B_DIM * 512 + (size_t)b * 512 + hh);
    }

    float4 acc[8];
#pragma unroll
    for (int j = 0; j < 8; j++) acc[j] = make_float4(0.f, 0.f, 0.f, 0.f);
    float m = -1e30f, l = 0.f;

    const float* base = rnn + (size_t)(chunk * CHUNK) * (B_DIM * H_DIM)
                            + (size_t)b * H_DIM;

    for (int s = 0; s < CHUNK; s++) {
        const float4* row =
            reinterpret_cast<const float4*>(base + (size_t)s * (B_DIM * H_DIM));
        float4 x[8];
#pragma unroll
        for (int j = 0; j < 8; j++) x[j] = row[j * 32 + lane];

        // partial dot
        float p = 0.f;
#pragma unroll
        for (int j = 0; j < 8; j++) {
            p += x[j].x * mrg[j].x + x[j].y * mrg[j].y +
                 x[j].z * mrg[j].z + x[j].w * mrg[j].w;
        }
        // warp-wide reduce (all lanes get the sum)
#pragma unroll
        for (int off = 16; off > 0; off >>= 1)
            p += __shfl_xor_sync(0xffffffffu, p, off);

        // online softmax update
        float mnew  = fmaxf(m, p);
        float scale = __expf(m - mnew);
        float w     = __expf(p - mnew);
#pragma unroll
        for (int j = 0; j < 8; j++) {
            acc[j].x = acc[j].x * scale + w * x[j].x;
            acc[j].y = acc[j].y * scale + w * x[j].y;
            acc[j].z = acc[j].z * scale + w * x[j].z;
            acc[j].w = acc[j].w * scale + w * x[j].w;
        }
        l = l * scale + w;
        m = mnew;
    }

    // write partial results
    float4* out4 = reinterpret_cast<float4*>(g_acc + (size_t)warp * H_DIM);
#pragma unroll
    for (int j = 0; j < 8; j++) out4[j * 32 + lane] = acc[j];
    if (lane == 0) {
        g_m[warp] = m;
        g_l[warp] = l;
    }
}

__global__ __launch_bounds__(256) void pass2(float* __restrict__ out) {
    const int b = blockIdx.x;
    const int tid = threadIdx.x;   // 256 threads, each owns 4 h's

    // Global max and denominator over this batch's SPLIT partials (redundant
    // per-thread compute; broadcast loads from L1 are cheap).
    float M = -1e30f;
#pragma unroll 4
    for (int c = 0; c < SPLIT; c++) M = fmaxf(M, g_m[b * SPLIT + c]);
    float L = 0.f;
#pragma unroll 4
    for (int c = 0; c < SPLIT; c++)
        L += g_l[b * SPLIT + c] * __expf(g_m[b * SPLIT + c] - M);

    float4 r = make_float4(0.f, 0.f, 0.f, 0.f);
#pragma unroll 4
    for (int c = 0; c < SPLIT; c++) {
        float w = __expf(g_m[b * SPLIT + c] - M);
        float4 a = *reinterpret_cast<const float4*>(
            g_acc + (size_t)(b * SPLIT + c) * H_DIM + tid * 4);
        r.x += w * a.x;
        r.y += w * a.y;
        r.z += w * a.z;
        r.w += w * a.w;
    }
    float inv = 1.f / L;
    r.x *= inv; r.y *= inv; r.z *= inv; r.w *= inv;
    reinterpret_cast<float4*>(out)[b * (H_DIM / 4) + tid] = r;
}

extern "C" void kernel_launch(void* const* d_in, const int* in_sizes, int n_in,
                              void* d_out, int out_size) {
    const float* rnn   = (const float*)d_in[0];
    const float* state = (const float*)d_in[1];
    float* out         = (float*)d_out;

    pass1<<<NPART / WARPS_PER_CTA, 256>>>(rnn, state);
    pass2<<<B_DIM, 256>>>(out);
}

// round 2
// speedup vs baseline: 1.6594x; 1.6594x over previous
#include <cuda_runtime.h>

// DotAttention: rnn_out [S,B,H] f32, state [2,2,B,H/2] f32 -> out [B,H,1] f32
// S=2048, B=32, H=1024.
// pass1: flash-style online-softmax partials, one warp per (b, 16-row chunk).
// pass0: combine per-chunk (m,l) into normalized per-chunk weights.
// pass2: weighted sum of partial accumulators, 512 CTAs.

#define S_LEN 2048
#define B_DIM 32
#define H_DIM 1024
#define SPLIT 128
#define CHUNK (S_LEN / SPLIT)          // 16 rows per warp
#define WARPS_PER_CTA 8
#define NPART (B_DIM * SPLIT)          // 4096 partials

__device__ float g_m[NPART];
__device__ float g_l[NPART];
__device__ float g_w[NPART];
__device__ float g_acc[(size_t)NPART * H_DIM];   // ~16.8 MB scratch

__global__ __launch_bounds__(256) void pass1(const float* __restrict__ rnn,
                                             const float* __restrict__ state) {
    const int warp = blockIdx.x * WARPS_PER_CTA + (threadIdx.x >> 5);
    const int lane = threadIdx.x & 31;
    const int b = warp / SPLIT;
    const int chunk = warp % SPLIT;

    // merged[b, h]: h = j*128 + lane*4; direction = h>>9
    float4 mrg[8];
#pragma unroll
    for (int j = 0; j < 8; j++) {
        int h = j * 128 + lane * 4;
        int d = h >> 9;
        int hh = h & 511;
        mrg[j] = *reinterpret_cast<const float4*>(
            state + (size_t)(2 + d) * B_DIM * 512 + (size_t)b * 512 + hh);
    }

    float4 acc[8];
#pragma unroll
    for (int j = 0; j < 8; j++) acc[j] = make_float4(0.f, 0.f, 0.f, 0.f);
    float m = -1e30f, l = 0.f;

    const float* base = rnn + (size_t)(chunk * CHUNK) * (B_DIM * H_DIM)
                            + (size_t)b * H_DIM;

    for (int s = 0; s < CHUNK; s++) {
        const float4* row =
            reinterpret_cast<const float4*>(base + (size_t)s * (B_DIM * H_DIM));
        float4 x[8];
#pragma unroll
        for (int j = 0; j < 8; j++) x[j] = row[j * 32 + lane];

        float p = 0.f;
#pragma unroll
        for (int j = 0; j < 8; j++) {
            p += x[j].x * mrg[j].x + x[j].y * mrg[j].y +
                 x[j].z * mrg[j].z + x[j].w * mrg[j].w;
        }
#pragma unroll
        for (int off = 16; off > 0; off >>= 1)
            p += __shfl_xor_sync(0xffffffffu, p, off);

        float mnew  = fmaxf(m, p);
        float scale = __expf(m - mnew);
        float w     = __expf(p - mnew);
#pragma unroll
        for (int j = 0; j < 8; j++) {
            acc[j].x = acc[j].x * scale + w * x[j].x;
            acc[j].y = acc[j].y * scale + w * x[j].y;
            acc[j].z = acc[j].z * scale + w * x[j].z;
            acc[j].w = acc[j].w * scale + w * x[j].w;
        }
        l = l * scale + w;
        m = mnew;
    }

    float4* out4 = reinterpret_cast<float4*>(g_acc + (size_t)warp * H_DIM);
#pragma unroll
    for (int j = 0; j < 8; j++) out4[j * 32 + lane] = acc[j];
    if (lane == 0) {
        g_m[warp] = m;
        g_l[warp] = l;
    }
}

// Combine (m,l) across the 128 chunks of each batch into normalized weights.
__global__ __launch_bounds__(128) void pass0() {
    const int b = blockIdx.x;
    const int c = threadIdx.x;           // 0..127
    const int lane = c & 31, wid = c >> 5;
    const int i = b * SPLIT + c;

    float m = g_m[i];
    float l = g_l[i];

    // block max
    float v = m;
#pragma unroll
    for (int off = 16; off > 0; off >>= 1)
        v = fmaxf(v, __shfl_xor_sync(0xffffffffu, v, off));
    __shared__ float s4[4];
    if (lane == 0) s4[wid] = v;
    __syncthreads();
    float M = fmaxf(fmaxf(s4[0], s4[1]), fmaxf(s4[2], s4[3]));

    float e  = __expf(m - M);
    float le = l * e;

    // block sum of le
    float s = le;
#pragma unroll
    for (int off = 16; off > 0; off >>= 1)
        s += __shfl_xor_sync(0xffffffffu, s, off);
    __shared__ float t4[4];
    if (lane == 0) t4[wid] = s;
    __syncthreads();
    float L = t4[0] + t4[1] + t4[2] + t4[3];

    g_w[i] = e / L;
}

// Weighted sum of partials. grid = (16 h-slices, 32 batches).
// Thread layout: hq = tid&15 (16 float4 within 64-float slice), cg = tid>>4.
__global__ __launch_bounds__(256) void pass2(float* __restrict__ out) {
    const int slice = blockIdx.x;        // 0..15
    const int b     = blockIdx.y;        // 0..31
    const int tid   = threadIdx.x;
    const int hq = tid & 15;
    const int cg = tid >> 4;             // 0..15, each covers 8 chunks

    __shared__ float sw[SPLIT];
    if (tid < SPLIT) sw[tid] = g_w[b * SPLIT + tid];
    __syncthreads();

    const float* base = g_acc + ((size_t)b * SPLIT) * H_DIM + slice * 64 + hq * 4;

    float rx = 0.f, ry = 0.f, rz = 0.f, rw = 0.f;
#pragma unroll
    for (int k = 0; k < 8; k++) {
        int chunk = cg * 8 + k;
        float4 a = *reinterpret_cast<const float4*>(base + (size_t)chunk * H_DIM);
        float w = sw[chunk];
        rx += w * a.x; ry += w * a.y; rz += w * a.z; rw += w * a.w;
    }

    __shared__ float4 red[256];
    red[tid] = make_float4(rx, ry, rz, rw);
    __syncthreads();
#pragma unroll
    for (int st = 8; st > 0; st >>= 1) {
        if (cg < st) {
            float4 o = red[tid + 16 * st];
            rx += o.x; ry += o.y; rz += o.z; rw += o.w;
            red[tid] = make_float4(rx, ry, rz, rw);
        }
        __syncthreads();
    }

    if (cg == 0) {
        reinterpret_cast<float4*>(out)[(b * H_DIM + slice * 64) / 4 + hq] =
            make_float4(rx, ry, rz, rw);
    }
}

extern "C" void kernel_launch(void* const* d_in, const int* in_sizes, int n_in,
                              void* d_out, int out_size) {
    const float* rnn   = (const float*)d_in[0];
    const float* state = (const float*)d_in[1];
    float* out         = (float*)d_out;

    pass1<<<NPART / WARPS_PER_CTA, 256>>>(rnn, state);
    pass0<<<B_DIM, 128>>>();
    dim3 g2(16, B_DIM);
    pass2<<<g2, 256>>>(out);
}